// round 1
// baseline (speedup 1.0000x reference)
#include <cuda_runtime.h>

// Problem constants (match setup_inputs)
#define B_   32
#define C_   128
#define H_   64
#define W_   64
#define O_   256
#define KH_  3
#define KW_  3
#define OH_  32
#define OW_  32
#define K_   (C_ * KH_ * KW_)   // 1152
#define M_   (B_ * OH_ * OW_)   // 32768 = 2^15

// Static device scratch (allocation-free rule: __device__ globals are allowed)
__device__ float g_patches[(size_t)K_ * M_];  // [k][m], m = b*1024 + p*32 + q  (~151 MB)
__device__ float g_wt[K_ * O_];               // [k][o]

// ---------------------------------------------------------------------------
// Kernel 1: bilinear im2col. One thread per (k, m) element; m is the fast
// index so writes are coalesced and x-row reads have high L1/L2 locality.
// ---------------------------------------------------------------------------
__global__ void im2col_kernel(const float* __restrict__ x,
                              const float* __restrict__ sh_p,
                              const float* __restrict__ sw_p)
{
    int idx = blockIdx.x * blockDim.x + threadIdx.x;   // 0 .. K_*M_-1
    int m = idx & (M_ - 1);
    int k = idx >> 15;

    float sh = __ldg(sh_p);
    float sw = __ldg(sw_p);

    int q = m & 31;
    int p = (m >> 5) & 31;
    int b = m >> 10;

    int c  = k / 9;
    int r  = k - c * 9;
    int kh = r / 3;
    int kw = r - kh * 3;

    float ph = (float)p * sh - 1.0f + (float)kh;
    float pw = (float)q * sw - 1.0f + (float)kw;
    float fh0 = floorf(ph), fw0 = floorf(pw);
    int h0 = (int)fh0, w0 = (int)fw0;
    float ah = ph - fh0, aw = pw - fw0;

    const float* xp = x + ((size_t)(b * C_ + c)) * (H_ * W_);

    bool h0v = (h0 >= 0) && (h0 < H_);
    bool h1v = (h0 + 1 >= 0) && (h0 + 1 < H_);
    bool w0v = (w0 >= 0) && (w0 < W_);
    bool w1v = (w0 + 1 >= 0) && (w0 + 1 < W_);

    float v00 = (h0v && w0v) ? xp[h0 * W_ + w0]           : 0.0f;
    float v01 = (h0v && w1v) ? xp[h0 * W_ + w0 + 1]       : 0.0f;
    float v10 = (h1v && w0v) ? xp[(h0 + 1) * W_ + w0]     : 0.0f;
    float v11 = (h1v && w1v) ? xp[(h0 + 1) * W_ + w0 + 1] : 0.0f;

    float val = (1.0f - ah) * ((1.0f - aw) * v00 + aw * v01)
              +          ah * ((1.0f - aw) * v10 + aw * v11);

    g_patches[idx] = val;
}

// ---------------------------------------------------------------------------
// Kernel 2: transpose weight [O][K] -> g_wt [K][O] (coalesced writes)
// ---------------------------------------------------------------------------
__global__ void wt_kernel(const float* __restrict__ w)
{
    int idx = blockIdx.x * blockDim.x + threadIdx.x;   // 0 .. K_*O_-1
    int o = idx & (O_ - 1);
    int k = idx >> 8;
    g_wt[idx] = w[o * K_ + k];
}

// ---------------------------------------------------------------------------
// Kernel 3: per-batch GEMM  out_b[O=256][PQ=1024] = Wt^T * P_b
//   A tile from g_wt[k][o], B tile from g_patches[k][b*1024+pq]
//   128x128x16 tiles, 256 threads, 8x8 per-thread accumulators,
//   double-buffered shared memory.
// ---------------------------------------------------------------------------
#define BM 128
#define BN 128
#define BK 16
#define NKT (K_ / BK)   // 72

__global__ __launch_bounds__(256, 2)
void gemm_kernel(const float* __restrict__ bias, float* __restrict__ out)
{
    __shared__ float As[2][BK][BM];
    __shared__ float Bs[2][BK][BN];

    const int bm  = blockIdx.x * BM;   // over O (2 tiles)
    const int bn  = blockIdx.y * BN;   // over pq (8 tiles)
    const int b   = blockIdx.z;        // batch
    const int tid = threadIdx.x;
    const int tx  = tid & 15;
    const int ty  = tid >> 4;

    const float* __restrict__ Ag = g_wt + bm;                        // + k*O_
    const float* __restrict__ Bg = g_patches + (size_t)b * 1024 + bn; // + k*M_

    // tile loader assignment: 512 float4 per 16x128 tile, 2 per thread
    const int ar0 = tid >> 5;        // rows 0..7
    const int ar1 = ar0 + 8;         // rows 8..15
    const int ac  = (tid & 31) * 4;  // col (float index)

    float4 na0, na1, nb0, nb1;

#define LOAD_G(k0)                                                          \
    na0 = *(const float4*)(Ag + (size_t)((k0) + ar0) * O_ + ac);            \
    na1 = *(const float4*)(Ag + (size_t)((k0) + ar1) * O_ + ac);            \
    nb0 = *(const float4*)(Bg + (size_t)((k0) + ar0) * M_ + ac);            \
    nb1 = *(const float4*)(Bg + (size_t)((k0) + ar1) * M_ + ac);

#define STORE_S(buf)                                                        \
    *(float4*)&As[buf][ar0][ac] = na0;                                      \
    *(float4*)&As[buf][ar1][ac] = na1;                                      \
    *(float4*)&Bs[buf][ar0][ac] = nb0;                                      \
    *(float4*)&Bs[buf][ar1][ac] = nb1;

    float acc[8][8];
#pragma unroll
    for (int i = 0; i < 8; i++)
#pragma unroll
        for (int j = 0; j < 8; j++) acc[i][j] = 0.0f;

    LOAD_G(0);
    STORE_S(0);
    __syncthreads();

    for (int kt = 0; kt < NKT; kt++) {
        const int cur = kt & 1;
        if (kt + 1 < NKT) { LOAD_G((kt + 1) * BK); }

#pragma unroll
        for (int kk = 0; kk < BK; kk++) {
            float4 a0 = *(const float4*)&As[cur][kk][ty * 8];
            float4 a1 = *(const float4*)&As[cur][kk][ty * 8 + 4];
            float4 b0 = *(const float4*)&Bs[cur][kk][tx * 8];
            float4 b1 = *(const float4*)&Bs[cur][kk][tx * 8 + 4];
            float a[8] = {a0.x, a0.y, a0.z, a0.w, a1.x, a1.y, a1.z, a1.w};
            float bb[8] = {b0.x, b0.y, b0.z, b0.w, b1.x, b1.y, b1.z, b1.w};
#pragma unroll
            for (int i = 0; i < 8; i++)
#pragma unroll
                for (int j = 0; j < 8; j++)
                    acc[i][j] = fmaf(a[i], bb[j], acc[i][j]);
        }

        if (kt + 1 < NKT) { STORE_S(cur ^ 1); }
        __syncthreads();
    }

    // Epilogue: out[b][o][pq], o = bm + ty*8 + i, pq = bn + tx*8 + j
    float* outb = out + (size_t)b * O_ * 1024;
#pragma unroll
    for (int i = 0; i < 8; i++) {
        int o = bm + ty * 8 + i;
        float bv = __ldg(bias + o);
        float* op = outb + (size_t)o * 1024 + bn + tx * 8;
        float4 r0 = make_float4(acc[i][0] + bv, acc[i][1] + bv,
                                acc[i][2] + bv, acc[i][3] + bv);
        float4 r1 = make_float4(acc[i][4] + bv, acc[i][5] + bv,
                                acc[i][6] + bv, acc[i][7] + bv);
        *(float4*)(op)     = r0;
        *(float4*)(op + 4) = r1;
    }
#undef LOAD_G
#undef STORE_S
}

// ---------------------------------------------------------------------------
extern "C" void kernel_launch(void* const* d_in, const int* in_sizes, int n_in,
                              void* d_out, int out_size)
{
    const float* x    = (const float*)d_in[0];
    const float* w    = (const float*)d_in[1];
    const float* bias = (const float*)d_in[2];
    const float* sh   = (const float*)d_in[3];
    const float* sw   = (const float*)d_in[4];
    float* out = (float*)d_out;

    im2col_kernel<<<(K_ * M_) / 256, 256>>>(x, sh, sw);
    wt_kernel<<<(K_ * O_) / 256, 256>>>(w);
    gemm_kernel<<<dim3(2, 8, B_), 256>>>(bias, out);
}

// round 3
// speedup vs baseline: 1.1186x; 1.1186x over previous
#include <cuda_runtime.h>
#include <cuda_bf16.h>
#include <cstdint>

// Problem constants
#define B_   32
#define C_   128
#define H_   64
#define W_   64
#define O_   256
#define K_   1152            // C*9
#define M_   32768           // B*32*32

// Static device scratch
__device__ __nv_bfloat16 g_pa_hi[(size_t)M_ * K_];   // patches hi, [m][k]
__device__ __nv_bfloat16 g_pa_lo[(size_t)M_ * K_];   // patches lo, [m][k]
__device__ __nv_bfloat16 g_wb_hi[O_ * K_];           // weight hi,  [o][k]
__device__ __nv_bfloat16 g_wb_lo[O_ * K_];           // weight lo,  [o][k]

// ---------------------------------------------------------------------------
// Kernel 1: bilinear im2col. One thread per (m, c); computes all 9 taps from
// a shared 4x4 neighborhood. Writes 9 contiguous bf16 per thread -> coalesced.
// ---------------------------------------------------------------------------
__global__ void im2col_kernel(const float* __restrict__ x,
                              const float* __restrict__ sh_p,
                              const float* __restrict__ sw_p)
{
    const int m = blockIdx.x;         // 0..32767
    const int c = threadIdx.x;        // 0..127

    float sh = __ldg(sh_p);
    float sw = __ldg(sw_p);

    const int q = m & 31;
    const int p = (m >> 5) & 31;
    const int b = m >> 10;

    float ph = (float)p * sh - 1.0f;
    float pw = (float)q * sw - 1.0f;
    float fh = floorf(ph), fw = floorf(pw);
    int h0 = (int)fh, w0 = (int)fw;
    float ah = ph - fh, aw = pw - fw;

    const float* xp = x + ((size_t)(b * C_ + c)) * (H_ * W_);

    float v[4][4];
#pragma unroll
    for (int r = 0; r < 4; r++) {
        int hr = h0 + r;
        bool hv = ((unsigned)hr < (unsigned)H_);
#pragma unroll
        for (int cc = 0; cc < 4; cc++) {
            int wc = w0 + cc;
            bool wv = ((unsigned)wc < (unsigned)W_);
            v[r][cc] = (hv && wv) ? xp[hr * W_ + wc] : 0.0f;
        }
    }

    // column interpolation (shared across kh)
    float cw[4][3];
#pragma unroll
    for (int r = 0; r < 4; r++)
#pragma unroll
        for (int kw = 0; kw < 3; kw++)
            cw[r][kw] = (1.0f - aw) * v[r][kw] + aw * v[r][kw + 1];

    const size_t base = (size_t)m * K_ + c * 9;
#pragma unroll
    for (int kh = 0; kh < 3; kh++)
#pragma unroll
        for (int kw = 0; kw < 3; kw++) {
            float val = (1.0f - ah) * cw[kh][kw] + ah * cw[kh + 1][kw];
            __nv_bfloat16 hi = __float2bfloat16(val);
            g_pa_hi[base + kh * 3 + kw] = hi;
            g_pa_lo[base + kh * 3 + kw] =
                __float2bfloat16(val - __bfloat162float(hi));
        }
}

// ---------------------------------------------------------------------------
// Kernel 2: weight fp32 [o][k] -> bf16 hi/lo [o][k]
// ---------------------------------------------------------------------------
__global__ void wsplit_kernel(const float* __restrict__ w)
{
    int idx = blockIdx.x * blockDim.x + threadIdx.x;
    float v = w[idx];
    __nv_bfloat16 hi = __float2bfloat16(v);
    g_wb_hi[idx] = hi;
    g_wb_lo[idx] = __float2bfloat16(v - __bfloat162float(hi));
}

// ---------------------------------------------------------------------------
// Kernel 3: bf16x3 GEMM via mma.sync.m16n8k16 (sm_80-class tensor path).
//   D[128m x 128n] per CTA; K=1152 in BK=32 stages, cp.async double buffer.
// ---------------------------------------------------------------------------
#define BK 32
#define NK (K_ / BK)            // 36
#define ROWB 80                 // padded row stride (64B data + 16B pad)
#define MAT_BYTES (128 * ROWB)  // 10240
#define STAGE_BYTES (4 * MAT_BYTES)   // Ah, Al, Bh, Bl -> 40960
#define SMEM_BYTES (2 * STAGE_BYTES)  // 81920

__device__ __forceinline__ uint32_t cvta_s(const void* p)
{
    uint32_t a;
    asm("{ .reg .u64 t; cvta.to.shared.u64 t, %1; cvt.u32.u64 %0, t; }"
        : "=r"(a) : "l"(p));
    return a;
}

__device__ __forceinline__ void cp16(uint32_t s, const void* g)
{
    asm volatile("cp.async.ca.shared.global [%0], [%1], 16;"
                 :: "r"(s), "l"(g));
}

__device__ __forceinline__ void ldsm4(uint32_t a, uint32_t* r)
{
    asm volatile("ldmatrix.sync.aligned.m8n8.x4.shared.b16 {%0,%1,%2,%3}, [%4];"
                 : "=r"(r[0]), "=r"(r[1]), "=r"(r[2]), "=r"(r[3]) : "r"(a));
}

__device__ __forceinline__ void mma16816(float* d, const uint32_t* a,
                                         const uint32_t* b)
{
    asm volatile(
        "mma.sync.aligned.m16n8k16.row.col.f32.bf16.bf16.f32 "
        "{%0,%1,%2,%3}, {%4,%5,%6,%7}, {%8,%9}, {%0,%1,%2,%3};"
        : "+f"(d[0]), "+f"(d[1]), "+f"(d[2]), "+f"(d[3])
        : "r"(a[0]), "r"(a[1]), "r"(a[2]), "r"(a[3]), "r"(b[0]), "r"(b[1]));
}

__global__ __launch_bounds__(512, 1)
void gemm_kernel(const float* __restrict__ bias, float* __restrict__ out)
{
    extern __shared__ char smem[];
    const uint32_t sbase = cvta_s(smem);

    const int tid  = threadIdx.x;
    const int lane = tid & 31;
    const int wid  = tid >> 5;
    const int m0   = blockIdx.y * 128;   // over M (pq)
    const int o0   = blockIdx.x * 128;   // over O

    // ---- cp.async loader mapping: 2048 16B chunks / 512 threads ----
    const int lrow = tid >> 2;           // 0..127
    const int lc   = tid & 3;            // chunk within 64B row
    const char* gA_h = (const char*)g_pa_hi + ((size_t)(m0 + lrow) * K_) * 2 + lc * 16;
    const char* gA_l = (const char*)g_pa_lo + ((size_t)(m0 + lrow) * K_) * 2 + lc * 16;
    const char* gB_h = (const char*)g_wb_hi + ((size_t)(o0 + lrow) * K_) * 2 + lc * 16;
    const char* gB_l = (const char*)g_wb_lo + ((size_t)(o0 + lrow) * K_) * 2 + lc * 16;
    const uint32_t soff = lrow * ROWB + lc * 16;

#define LOAD_STAGE(stage, buf)                                                 \
    {                                                                          \
        const uint32_t sb = sbase + (buf) * STAGE_BYTES + soff;                \
        const size_t go = (size_t)(stage) * (BK * 2);                          \
        cp16(sb,                 gA_h + go);                                   \
        cp16(sb + MAT_BYTES,     gA_l + go);                                   \
        cp16(sb + 2 * MAT_BYTES, gB_h + go);                                   \
        cp16(sb + 3 * MAT_BYTES, gB_l + go);                                   \
    }

    // ---- warp tiling: 4 (m) x 4 (n) warps; warp tile 32m x 32n ----
    const int wm = (wid & 3) * 32;
    const int wn = (wid >> 2) * 32;

    // ldmatrix lane addressing (byte offsets within a matrix buffer)
    const int a_row = lane & 15;                 // + i*16 + wm
    const int a_col = (lane >> 4) << 3;          // + kk    (elements)
    const int b_row = (lane & 7) + ((lane >> 4) << 3);   // + j2*16 + wn
    const int b_col = lane & 8;                  // + kk

    float acc[2][4][4];
#pragma unroll
    for (int i = 0; i < 2; i++)
#pragma unroll
        for (int j = 0; j < 4; j++)
#pragma unroll
            for (int r = 0; r < 4; r++) acc[i][j][r] = 0.0f;

    // ---- prologue ----
    LOAD_STAGE(0, 0);
    asm volatile("cp.async.commit_group;");
    LOAD_STAGE(1, 1);
    asm volatile("cp.async.commit_group;");

    for (int it = 0; it < NK; it++) {
        asm volatile("cp.async.wait_group 1;");
        __syncthreads();

        const uint32_t stg = sbase + (it & 1) * STAGE_BYTES;
        const uint32_t sAh = stg;
        const uint32_t sAl = stg + MAT_BYTES;
        const uint32_t sBh = stg + 2 * MAT_BYTES;
        const uint32_t sBl = stg + 3 * MAT_BYTES;

#pragma unroll
        for (int ks = 0; ks < 2; ks++) {
            const int kk = ks * 16;
            uint32_t ah[2][4], al[2][4], bh[2][4], bl[2][4];
#pragma unroll
            for (int i = 0; i < 2; i++) {
                uint32_t off = (uint32_t)((wm + i * 16 + a_row) * ROWB
                                          + (kk + a_col) * 2);
                ldsm4(sAh + off, ah[i]);
                ldsm4(sAl + off, al[i]);
            }
#pragma unroll
            for (int j2 = 0; j2 < 2; j2++) {
                uint32_t off = (uint32_t)((wn + j2 * 16 + b_row) * ROWB
                                          + (kk + b_col) * 2);
                ldsm4(sBh + off, bh[j2]);
                ldsm4(sBl + off, bl[j2]);
            }
#pragma unroll
            for (int i = 0; i < 2; i++)
#pragma unroll
                for (int j = 0; j < 4; j++) {
                    const uint32_t* pbh = &bh[j >> 1][(j & 1) * 2];
                    const uint32_t* pbl = &bl[j >> 1][(j & 1) * 2];
                    mma16816(acc[i][j], ah[i], pbh);   // Ah*Bh
                    mma16816(acc[i][j], al[i], pbh);   // Al*Bh
                    mma16816(acc[i][j], ah[i], pbl);   // Ah*Bl
                }
        }

        __syncthreads();
        if (it + 2 < NK) LOAD_STAGE(it + 2, it & 1);
        asm volatile("cp.async.commit_group;");
    }

    // ---- epilogue: stage through smem for coalesced stores ----
    __syncthreads();
    float* eb = (float*)smem;            // [o_local][m_local], stride 132
#pragma unroll
    for (int i = 0; i < 2; i++) {
        int ml = wm + i * 16 + (lane >> 2);
#pragma unroll
        for (int j = 0; j < 4; j++) {
            int ol = wn + j * 8 + (lane & 3) * 2;
            eb[(size_t)ol * 132 + ml]           = acc[i][j][0];
            eb[(size_t)(ol + 1) * 132 + ml]     = acc[i][j][1];
            eb[(size_t)ol * 132 + ml + 8]       = acc[i][j][2];
            eb[(size_t)(ol + 1) * 132 + ml + 8] = acc[i][j][3];
        }
    }
    __syncthreads();

    const int oo   = tid >> 2;           // 0..127
    const int quad = tid & 3;            // 0..3 -> 32 m each
    const float bv = __ldg(bias + o0 + oo);
    const int bidx = m0 >> 10;
    const int pq0  = m0 & 1023;
    float* op = out + (size_t)bidx * (O_ * 1024)
              + (size_t)(o0 + oo) * 1024 + pq0 + quad * 32;
    const float* sp = eb + (size_t)oo * 132 + quad * 32;
#pragma unroll
    for (int i = 0; i < 8; i++) {
        float4 vv = *(const float4*)(sp + i * 4);
        vv.x += bv; vv.y += bv; vv.z += bv; vv.w += bv;
        *(float4*)(op + i * 4) = vv;
    }
#undef LOAD_STAGE
}

// ---------------------------------------------------------------------------
extern "C" void kernel_launch(void* const* d_in, const int* in_sizes, int n_in,
                              void* d_out, int out_size)
{
    const float* x    = (const float*)d_in[0];
    const float* w    = (const float*)d_in[1];
    const float* bias = (const float*)d_in[2];
    const float* sh   = (const float*)d_in[3];
    const float* sw   = (const float*)d_in[4];
    float* out = (float*)d_out;

    im2col_kernel<<<M_, C_>>>(x, sh, sw);
    wsplit_kernel<<<(O_ * K_) / 256, 256>>>(w);

    cudaFuncSetAttribute(gemm_kernel,
                         cudaFuncAttributeMaxDynamicSharedMemorySize, SMEM_BYTES);
    gemm_kernel<<<dim3(2, 256), 512, SMEM_BYTES>>>(bias, out);
}

// round 4
// speedup vs baseline: 2.1471x; 1.9194x over previous
#include <cuda_runtime.h>
#include <cuda_bf16.h>
#include <cstdint>

// Problem constants
#define B_   32
#define C_   128
#define H_   64
#define W_   64
#define O_   256
#define K_   1152            // C*9
#define M_   32768           // B*32*32

// Static device scratch
__device__ __nv_bfloat16 g_pa_hi[(size_t)M_ * K_];   // patches hi, [m][k]
__device__ __nv_bfloat16 g_pa_lo[(size_t)M_ * K_];   // patches lo, [m][k]
__device__ __nv_bfloat16 g_wb_hi[O_ * K_];           // weight hi,  [o][k]
__device__ __nv_bfloat16 g_wb_lo[O_ * K_];           // weight lo,  [o][k]

// ---------------------------------------------------------------------------
// Kernel 1: bilinear im2col, smem-staged for full coalescing.
//   Block = (b, p). 4 chunks of 32 channels:
//     phase1: coalesced load of x rows h0..h0+3, all 64 w, 32 c  -> smem
//     phase2: per (q,c) compute 9 taps from smem (fracs shared across taps)
//     phase3: coalesced uint2 stores of 288 contiguous bf16 per (q, chunk)
// ---------------------------------------------------------------------------
#define OUT_STRIDE 292   // bf16 per staged q-row (288 data + 4 pad; 584B, 8B-aligned)
#define XS_BYTES   32768                       // 32c * 4r * 64w floats
#define IM2COL_SMEM (XS_BYTES + 2 * 32 * OUT_STRIDE * 2)   // 70144

__global__ __launch_bounds__(256, 3)
void im2col_kernel(const float* __restrict__ x,
                   const float* __restrict__ sh_p,
                   const float* __restrict__ sw_p)
{
    extern __shared__ char sm[];
    float* xs = (float*)sm;                                   // [c][4][64]
    __nv_bfloat16* ohi = (__nv_bfloat16*)(sm + XS_BYTES);     // [32][OUT_STRIDE]
    __nv_bfloat16* olo = ohi + 32 * OUT_STRIDE;

    const int t = threadIdx.x;
    const int b = blockIdx.x >> 5;
    const int p = blockIdx.x & 31;

    const float sh = __ldg(sh_p);
    const float sw = __ldg(sw_p);

    const float ph = (float)p * sh - 1.0f;
    const float fh = floorf(ph);
    const int   h0 = (int)fh;
    const float ah = ph - fh;

    const int q  = t & 31;
    const int cg = t >> 5;           // 0..7
    const float pw = (float)q * sw - 1.0f;
    const float fw = floorf(pw);
    const int   w0 = (int)fw;
    const float aw = pw - fw;

    for (int cc = 0; cc < 4; cc++) {
        const int c0 = cc * 32;

        // ---- phase 1: coalesced x load ----
        {
            const float4* xg = (const float4*)x;
            for (int i = t; i < 2048; i += 256) {
                const int cl  = i >> 6;
                const int rem = i & 63;
                const int r   = rem >> 4;
                const int w4  = rem & 15;
                const int hr  = h0 + r;
                float4 v = make_float4(0.f, 0.f, 0.f, 0.f);
                if ((unsigned)hr < (unsigned)H_)
                    v = xg[((size_t)(b * C_ + c0 + cl) * H_ + hr) * 16 + w4];
                ((float4*)xs)[i] = v;
            }
        }
        __syncthreads();

        // ---- phase 2: compute 9 taps for 4 channels per thread ----
#pragma unroll
        for (int i = 0; i < 4; i++) {
            const int cl = cg * 4 + i;
            const float* xr = xs + cl * 256;

            float v[4][4];
#pragma unroll
            for (int r = 0; r < 4; r++)
#pragma unroll
                for (int j = 0; j < 4; j++) {
                    const int wc = w0 + j;
                    v[r][j] = ((unsigned)wc < (unsigned)W_) ? xr[r * 64 + wc] : 0.0f;
                }

            float cwv[4][3];
#pragma unroll
            for (int r = 0; r < 4; r++)
#pragma unroll
                for (int kw = 0; kw < 3; kw++)
                    cwv[r][kw] = (1.0f - aw) * v[r][kw] + aw * v[r][kw + 1];

            __nv_bfloat16* oh = ohi + q * OUT_STRIDE + cl * 9;
            __nv_bfloat16* ol = olo + q * OUT_STRIDE + cl * 9;
#pragma unroll
            for (int kh = 0; kh < 3; kh++)
#pragma unroll
                for (int kw = 0; kw < 3; kw++) {
                    const float val = (1.0f - ah) * cwv[kh][kw] + ah * cwv[kh + 1][kw];
                    const __nv_bfloat16 hi = __float2bfloat16(val);
                    oh[kh * 3 + kw] = hi;
                    ol[kh * 3 + kw] = __float2bfloat16(val - __bfloat162float(hi));
                }
        }
        __syncthreads();

        // ---- phase 3: coalesced store (72 uint2 per q per array) ----
        {
            const size_t mrow = (size_t)(b * 1024 + p * 32);
            for (int i = t; i < 2304; i += 256) {
                const int qq = i / 72;
                const int j  = i - qq * 72;
                const uint2 vh = *(const uint2*)((const char*)ohi + qq * (OUT_STRIDE * 2) + j * 8);
                const uint2 vl = *(const uint2*)((const char*)olo + qq * (OUT_STRIDE * 2) + j * 8);
                const size_t gd = ((mrow + qq) * K_ + c0 * 9) * 2 + j * 8;   // bytes
                *(uint2*)((char*)g_pa_hi + gd) = vh;
                *(uint2*)((char*)g_pa_lo + gd) = vl;
            }
        }
        __syncthreads();
    }
}

// ---------------------------------------------------------------------------
// Kernel 2: weight fp32 [o][k] -> bf16 hi/lo [o][k]
// ---------------------------------------------------------------------------
__global__ void wsplit_kernel(const float* __restrict__ w)
{
    int idx = blockIdx.x * blockDim.x + threadIdx.x;
    float v = w[idx];
    __nv_bfloat16 hi = __float2bfloat16(v);
    g_wb_hi[idx] = hi;
    g_wb_lo[idx] = __float2bfloat16(v - __bfloat162float(hi));
}

// ---------------------------------------------------------------------------
// Kernel 3: bf16x3 GEMM via mma.sync.m16n8k16 (unchanged from R3)
// ---------------------------------------------------------------------------
#define BK 32
#define NK (K_ / BK)            // 36
#define ROWB 80                 // padded row stride (64B data + 16B pad)
#define MAT_BYTES (128 * ROWB)  // 10240
#define STAGE_BYTES (4 * MAT_BYTES)   // 40960
#define SMEM_BYTES (2 * STAGE_BYTES)  // 81920

__device__ __forceinline__ uint32_t cvta_s(const void* p)
{
    uint32_t a;
    asm("{ .reg .u64 t; cvta.to.shared.u64 t, %1; cvt.u32.u64 %0, t; }"
        : "=r"(a) : "l"(p));
    return a;
}

__device__ __forceinline__ void cp16(uint32_t s, const void* g)
{
    asm volatile("cp.async.ca.shared.global [%0], [%1], 16;"
                 :: "r"(s), "l"(g));
}

__device__ __forceinline__ void ldsm4(uint32_t a, uint32_t* r)
{
    asm volatile("ldmatrix.sync.aligned.m8n8.x4.shared.b16 {%0,%1,%2,%3}, [%4];"
                 : "=r"(r[0]), "=r"(r[1]), "=r"(r[2]), "=r"(r[3]) : "r"(a));
}

__device__ __forceinline__ void mma16816(float* d, const uint32_t* a,
                                         const uint32_t* b)
{
    asm volatile(
        "mma.sync.aligned.m16n8k16.row.col.f32.bf16.bf16.f32 "
        "{%0,%1,%2,%3}, {%4,%5,%6,%7}, {%8,%9}, {%0,%1,%2,%3};"
        : "+f"(d[0]), "+f"(d[1]), "+f"(d[2]), "+f"(d[3])
        : "r"(a[0]), "r"(a[1]), "r"(a[2]), "r"(a[3]), "r"(b[0]), "r"(b[1]));
}

__global__ __launch_bounds__(512, 1)
void gemm_kernel(const float* __restrict__ bias, float* __restrict__ out)
{
    extern __shared__ char smem[];
    const uint32_t sbase = cvta_s(smem);

    const int tid  = threadIdx.x;
    const int lane = tid & 31;
    const int wid  = tid >> 5;
    const int m0   = blockIdx.y * 128;
    const int o0   = blockIdx.x * 128;

    const int lrow = tid >> 2;
    const int lc   = tid & 3;
    const char* gA_h = (const char*)g_pa_hi + ((size_t)(m0 + lrow) * K_) * 2 + lc * 16;
    const char* gA_l = (const char*)g_pa_lo + ((size_t)(m0 + lrow) * K_) * 2 + lc * 16;
    const char* gB_h = (const char*)g_wb_hi + ((size_t)(o0 + lrow) * K_) * 2 + lc * 16;
    const char* gB_l = (const char*)g_wb_lo + ((size_t)(o0 + lrow) * K_) * 2 + lc * 16;
    const uint32_t soff = lrow * ROWB + lc * 16;

#define LOAD_STAGE(stage, buf)                                                 \
    {                                                                          \
        const uint32_t sb = sbase + (buf) * STAGE_BYTES + soff;                \
        const size_t go = (size_t)(stage) * (BK * 2);                          \
        cp16(sb,                 gA_h + go);                                   \
        cp16(sb + MAT_BYTES,     gA_l + go);                                   \
        cp16(sb + 2 * MAT_BYTES, gB_h + go);                                   \
        cp16(sb + 3 * MAT_BYTES, gB_l + go);                                   \
    }

    const int wm = (wid & 3) * 32;
    const int wn = (wid >> 2) * 32;

    const int a_row = lane & 15;
    const int a_col = (lane >> 4) << 3;
    const int b_row = (lane & 7) + ((lane >> 4) << 3);
    const int b_col = lane & 8;

    float acc[2][4][4];
#pragma unroll
    for (int i = 0; i < 2; i++)
#pragma unroll
        for (int j = 0; j < 4; j++)
#pragma unroll
            for (int r = 0; r < 4; r++) acc[i][j][r] = 0.0f;

    LOAD_STAGE(0, 0);
    asm volatile("cp.async.commit_group;");
    LOAD_STAGE(1, 1);
    asm volatile("cp.async.commit_group;");

    for (int it = 0; it < NK; it++) {
        asm volatile("cp.async.wait_group 1;");
        __syncthreads();

        const uint32_t stg = sbase + (it & 1) * STAGE_BYTES;
        const uint32_t sAh = stg;
        const uint32_t sAl = stg + MAT_BYTES;
        const uint32_t sBh = stg + 2 * MAT_BYTES;
        const uint32_t sBl = stg + 3 * MAT_BYTES;

#pragma unroll
        for (int ks = 0; ks < 2; ks++) {
            const int kk = ks * 16;
            uint32_t ah[2][4], al[2][4], bh[2][4], bl[2][4];
#pragma unroll
            for (int i = 0; i < 2; i++) {
                uint32_t off = (uint32_t)((wm + i * 16 + a_row) * ROWB
                                          + (kk + a_col) * 2);
                ldsm4(sAh + off, ah[i]);
                ldsm4(sAl + off, al[i]);
            }
#pragma unroll
            for (int j2 = 0; j2 < 2; j2++) {
                uint32_t off = (uint32_t)((wn + j2 * 16 + b_row) * ROWB
                                          + (kk + b_col) * 2);
                ldsm4(sBh + off, bh[j2]);
                ldsm4(sBl + off, bl[j2]);
            }
#pragma unroll
            for (int i = 0; i < 2; i++)
#pragma unroll
                for (int j = 0; j < 4; j++) {
                    const uint32_t* pbh = &bh[j >> 1][(j & 1) * 2];
                    const uint32_t* pbl = &bl[j >> 1][(j & 1) * 2];
                    mma16816(acc[i][j], ah[i], pbh);
                    mma16816(acc[i][j], al[i], pbh);
                    mma16816(acc[i][j], ah[i], pbl);
                }
        }

        __syncthreads();
        if (it + 2 < NK) LOAD_STAGE(it + 2, it & 1);
        asm volatile("cp.async.commit_group;");
    }

    __syncthreads();
    float* eb = (float*)smem;
#pragma unroll
    for (int i = 0; i < 2; i++) {
        int ml = wm + i * 16 + (lane >> 2);
#pragma unroll
        for (int j = 0; j < 4; j++) {
            int ol = wn + j * 8 + (lane & 3) * 2;
            eb[(size_t)ol * 132 + ml]           = acc[i][j][0];
            eb[(size_t)(ol + 1) * 132 + ml]     = acc[i][j][1];
            eb[(size_t)ol * 132 + ml + 8]       = acc[i][j][2];
            eb[(size_t)(ol + 1) * 132 + ml + 8] = acc[i][j][3];
        }
    }
    __syncthreads();

    const int oo   = tid >> 2;
    const int quad = tid & 3;
    const float bv = __ldg(bias + o0 + oo);
    const int bidx = m0 >> 10;
    const int pq0  = m0 & 1023;
    float* op = out + (size_t)bidx * (O_ * 1024)
              + (size_t)(o0 + oo) * 1024 + pq0 + quad * 32;
    const float* sp = eb + (size_t)oo * 132 + quad * 32;
#pragma unroll
    for (int i = 0; i < 8; i++) {
        float4 vv = *(const float4*)(sp + i * 4);
        vv.x += bv; vv.y += bv; vv.z += bv; vv.w += bv;
        *(float4*)(op + i * 4) = vv;
    }
#undef LOAD_STAGE
}

// ---------------------------------------------------------------------------
extern "C" void kernel_launch(void* const* d_in, const int* in_sizes, int n_in,
                              void* d_out, int out_size)
{
    const float* x    = (const float*)d_in[0];
    const float* w    = (const float*)d_in[1];
    const float* bias = (const float*)d_in[2];
    const float* sh   = (const float*)d_in[3];
    const float* sw   = (const float*)d_in[4];
    float* out = (float*)d_out;

    cudaFuncSetAttribute(im2col_kernel,
                         cudaFuncAttributeMaxDynamicSharedMemorySize, IM2COL_SMEM);
    cudaFuncSetAttribute(gemm_kernel,
                         cudaFuncAttributeMaxDynamicSharedMemorySize, SMEM_BYTES);

    im2col_kernel<<<1024, 256, IM2COL_SMEM>>>(x, sh, sw);
    wsplit_kernel<<<(O_ * K_) / 256, 256>>>(w);
    gemm_kernel<<<dim3(2, 256), 512, SMEM_BYTES>>>(bias, out);
}

// round 7
// speedup vs baseline: 3.4963x; 1.6284x over previous
#include <cuda_runtime.h>
#include <cuda_fp16.h>
#include <cstdint>

// Problem constants
#define B_   32
#define C_   128
#define H_   64
#define W_   64
#define O_   256
#define K_   1152            // C*9
#define M_   32768           // B*32*32

// Static device scratch
__device__ __half g_pa[(size_t)M_ * K_];   // patches fp16, [m][k]
__device__ __half g_wb[O_ * K_];           // weight fp16,  [o][k]

// ---------------------------------------------------------------------------
// Kernel 1: bilinear im2col, smem-staged, fp16 output.
// ---------------------------------------------------------------------------
#define OUT_STRIDE 292   // fp16 per staged q-row (288 data + 4 pad)
#define XS_BYTES   32768
#define IM2COL_SMEM (XS_BYTES + 32 * OUT_STRIDE * 2)   // 51456

__global__ __launch_bounds__(256, 4)
void im2col_kernel(const float* __restrict__ x,
                   const float* __restrict__ sh_p,
                   const float* __restrict__ sw_p)
{
    extern __shared__ char sm[];
    float* xs = (float*)sm;                              // [c][4][64]
    __half* ohi = (__half*)(sm + XS_BYTES);              // [32][OUT_STRIDE]

    const int t = threadIdx.x;
    const int b = blockIdx.x >> 5;
    const int p = blockIdx.x & 31;

    const float sh = __ldg(sh_p);
    const float sw = __ldg(sw_p);

    const float ph = (float)p * sh - 1.0f;
    const float fh = floorf(ph);
    const int   h0 = (int)fh;
    const float ah = ph - fh;

    const int q  = t & 31;
    const int cg = t >> 5;           // 0..7
    const float pw = (float)q * sw - 1.0f;
    const float fw = floorf(pw);
    const int   w0 = (int)fw;
    const float aw = pw - fw;

    for (int cc = 0; cc < 4; cc++) {
        const int c0 = cc * 32;

        // ---- phase 1: coalesced x load ----
        {
            const float4* xg = (const float4*)x;
            for (int i = t; i < 2048; i += 256) {
                const int cl  = i >> 6;
                const int rem = i & 63;
                const int r   = rem >> 4;
                const int w4  = rem & 15;
                const int hr  = h0 + r;
                float4 v = make_float4(0.f, 0.f, 0.f, 0.f);
                if ((unsigned)hr < (unsigned)H_)
                    v = xg[((size_t)(b * C_ + c0 + cl) * H_ + hr) * 16 + w4];
                ((float4*)xs)[i] = v;
            }
        }
        __syncthreads();

        // ---- phase 2: compute 9 taps for 4 channels per thread ----
#pragma unroll
        for (int i = 0; i < 4; i++) {
            const int cl = cg * 4 + i;
            const float* xr = xs + cl * 256;

            float v[4][4];
#pragma unroll
            for (int r = 0; r < 4; r++)
#pragma unroll
                for (int j = 0; j < 4; j++) {
                    const int wc = w0 + j;
                    v[r][j] = ((unsigned)wc < (unsigned)W_) ? xr[r * 64 + wc] : 0.0f;
                }

            float cwv[4][3];
#pragma unroll
            for (int r = 0; r < 4; r++)
#pragma unroll
                for (int kw = 0; kw < 3; kw++)
                    cwv[r][kw] = (1.0f - aw) * v[r][kw] + aw * v[r][kw + 1];

            __half* oh = ohi + q * OUT_STRIDE + cl * 9;
#pragma unroll
            for (int kh = 0; kh < 3; kh++)
#pragma unroll
                for (int kw = 0; kw < 3; kw++) {
                    const float val = (1.0f - ah) * cwv[kh][kw] + ah * cwv[kh + 1][kw];
                    oh[kh * 3 + kw] = __float2half_rn(val);
                }
        }
        __syncthreads();

        // ---- phase 3: coalesced store (72 uint2 per q) ----
        {
            const size_t mrow = (size_t)(b * 1024 + p * 32);
            for (int i = t; i < 2304; i += 256) {
                const int qq = i / 72;
                const int j  = i - qq * 72;
                const uint2 vh = *(const uint2*)((const char*)ohi + qq * (OUT_STRIDE * 2) + j * 8);
                const size_t gd = ((mrow + qq) * K_ + c0 * 9) * 2 + j * 8;   // bytes
                *(uint2*)((char*)g_pa + gd) = vh;
            }
        }
        __syncthreads();
    }
}

// ---------------------------------------------------------------------------
// Kernel 2: weight fp32 [o][k] -> fp16 [o][k]
// ---------------------------------------------------------------------------
__global__ void wconv_kernel(const float* __restrict__ w)
{
    int idx = blockIdx.x * blockDim.x + threadIdx.x;
    g_wb[idx] = __float2half_rn(w[idx]);
}

// ---------------------------------------------------------------------------
// Kernel 3: fp16 GEMM via mma.sync.m16n8k16, 3-stage cp.async pipeline.
//   D[128m x 128n] per CTA; K=1152 in BK=32 stages.
//   Invariant: exactly ONE commit_group per iteration (empty groups allowed)
//   so wait_group 1 at iter `it` guarantees stage `it` has landed.
// ---------------------------------------------------------------------------
#define BK 32
#define NK (K_ / BK)            // 36
#define ROWB 80                 // padded row stride (64B data + 16B pad)
#define MAT_BYTES (128 * ROWB)  // 10240
#define STAGE_BYTES (2 * MAT_BYTES)   // A, B -> 20480
#define SMEM_BYTES 69632        // max(3*STAGE_BYTES=61440, epilogue 67584) + pad

__device__ __forceinline__ uint32_t cvta_s(const void* p)
{
    uint32_t a;
    asm("{ .reg .u64 t; cvta.to.shared.u64 t, %1; cvt.u32.u64 %0, t; }"
        : "=r"(a) : "l"(p));
    return a;
}

__device__ __forceinline__ void cp16(uint32_t s, const void* g)
{
    asm volatile("cp.async.ca.shared.global [%0], [%1], 16;"
                 :: "r"(s), "l"(g));
}

__device__ __forceinline__ void ldsm4(uint32_t a, uint32_t* r)
{
    asm volatile("ldmatrix.sync.aligned.m8n8.x4.shared.b16 {%0,%1,%2,%3}, [%4];"
                 : "=r"(r[0]), "=r"(r[1]), "=r"(r[2]), "=r"(r[3]) : "r"(a));
}

__device__ __forceinline__ void mma16816(float* d, const uint32_t* a,
                                         const uint32_t* b)
{
    asm volatile(
        "mma.sync.aligned.m16n8k16.row.col.f32.f16.f16.f32 "
        "{%0,%1,%2,%3}, {%4,%5,%6,%7}, {%8,%9}, {%0,%1,%2,%3};"
        : "+f"(d[0]), "+f"(d[1]), "+f"(d[2]), "+f"(d[3])
        : "r"(a[0]), "r"(a[1]), "r"(a[2]), "r"(a[3]), "r"(b[0]), "r"(b[1]));
}

__global__ __launch_bounds__(512, 1)
void gemm_kernel(const float* __restrict__ bias, float* __restrict__ out)
{
    extern __shared__ char smem[];
    const uint32_t sbase = cvta_s(smem);

    const int tid  = threadIdx.x;
    const int lane = tid & 31;
    const int wid  = tid >> 5;
    const int m0   = blockIdx.y * 128;
    const int o0   = blockIdx.x * 128;

    // cp.async loader mapping: 1024 16B chunks per stage / 512 threads
    const int lrow = tid >> 2;
    const int lc   = tid & 3;
    const char* gA = (const char*)g_pa + ((size_t)(m0 + lrow) * K_) * 2 + lc * 16;
    const char* gB = (const char*)g_wb + ((size_t)(o0 + lrow) * K_) * 2 + lc * 16;
    const uint32_t soff = lrow * ROWB + lc * 16;

#define LOAD_STAGE(stage, buf)                                                 \
    {                                                                          \
        const uint32_t sb = sbase + (buf) * STAGE_BYTES + soff;                \
        const size_t go = (size_t)(stage) * (BK * 2);                          \
        cp16(sb,             gA + go);                                         \
        cp16(sb + MAT_BYTES, gB + go);                                         \
    }

    const int wm = (wid & 3) * 32;
    const int wn = (wid >> 2) * 32;

    const int a_row = lane & 15;
    const int a_col = (lane >> 4) << 3;
    const int b_row = (lane & 7) + ((lane >> 4) << 3);
    const int b_col = lane & 8;

    float acc[2][4][4];
#pragma unroll
    for (int i = 0; i < 2; i++)
#pragma unroll
        for (int j = 0; j < 4; j++)
#pragma unroll
            for (int r = 0; r < 4; r++) acc[i][j][r] = 0.0f;

    LOAD_STAGE(0, 0);
    asm volatile("cp.async.commit_group;");
    LOAD_STAGE(1, 1);
    asm volatile("cp.async.commit_group;");

    for (int it = 0; it < NK; it++) {
        asm volatile("cp.async.wait_group 1;");
        __syncthreads();

        const uint32_t stg = sbase + (it % 3) * STAGE_BYTES;
        const uint32_t sA = stg;
        const uint32_t sB = stg + MAT_BYTES;

#pragma unroll
        for (int ks = 0; ks < 2; ks++) {
            const int kk = ks * 16;
            uint32_t a[2][4], bfr[2][4];
#pragma unroll
            for (int i = 0; i < 2; i++) {
                uint32_t off = (uint32_t)((wm + i * 16 + a_row) * ROWB
                                          + (kk + a_col) * 2);
                ldsm4(sA + off, a[i]);
            }
#pragma unroll
            for (int j2 = 0; j2 < 2; j2++) {
                uint32_t off = (uint32_t)((wn + j2 * 16 + b_row) * ROWB
                                          + (kk + b_col) * 2);
                ldsm4(sB + off, bfr[j2]);
            }
#pragma unroll
            for (int i = 0; i < 2; i++)
#pragma unroll
                for (int j = 0; j < 4; j++)
                    mma16816(acc[i][j], a[i], &bfr[j >> 1][(j & 1) * 2]);
        }

        // Consumed stage `it`; its buffer (it%3) is now free for stage it+2.
        __syncthreads();
        if (it + 2 < NK) LOAD_STAGE(it + 2, (it + 2) % 3);
        asm volatile("cp.async.commit_group;");   // exactly one commit per iter
    }

    // All cp.async consumed (wait_group at it=NK-1 + empty tail commits).
    asm volatile("cp.async.wait_group 0;");
    __syncthreads();

    // ---- epilogue: stage through smem for coalesced stores ----
    float* eb = (float*)smem;            // [o_local][m_local], stride 132
#pragma unroll
    for (int i = 0; i < 2; i++) {
        int ml = wm + i * 16 + (lane >> 2);
#pragma unroll
        for (int j = 0; j < 4; j++) {
            int ol = wn + j * 8 + (lane & 3) * 2;
            eb[(size_t)ol * 132 + ml]           = acc[i][j][0];
            eb[(size_t)(ol + 1) * 132 + ml]     = acc[i][j][1];
            eb[(size_t)ol * 132 + ml + 8]       = acc[i][j][2];
            eb[(size_t)(ol + 1) * 132 + ml + 8] = acc[i][j][3];
        }
    }
    __syncthreads();

    const int oo   = tid >> 2;
    const int quad = tid & 3;
    const float bv = __ldg(bias + o0 + oo);
    const int bidx = m0 >> 10;
    const int pq0  = m0 & 1023;
    float* op = out + (size_t)bidx * (O_ * 1024)
              + (size_t)(o0 + oo) * 1024 + pq0 + quad * 32;
    const float* sp = eb + (size_t)oo * 132 + quad * 32;
#pragma unroll
    for (int i = 0; i < 8; i++) {
        float4 vv = *(const float4*)(sp + i * 4);
        vv.x += bv; vv.y += bv; vv.z += bv; vv.w += bv;
        *(float4*)(op + i * 4) = vv;
    }
#undef LOAD_STAGE
}

// ---------------------------------------------------------------------------
extern "C" void kernel_launch(void* const* d_in, const int* in_sizes, int n_in,
                              void* d_out, int out_size)
{
    const float* x    = (const float*)d_in[0];
    const float* w    = (const float*)d_in[1];
    const float* bias = (const float*)d_in[2];
    const float* sh   = (const float*)d_in[3];
    const float* sw   = (const float*)d_in[4];
    float* out = (float*)d_out;

    cudaFuncSetAttribute(im2col_kernel,
                         cudaFuncAttributeMaxDynamicSharedMemorySize, IM2COL_SMEM);
    cudaFuncSetAttribute(gemm_kernel,
                         cudaFuncAttributeMaxDynamicSharedMemorySize, SMEM_BYTES);

    im2col_kernel<<<1024, 256, IM2COL_SMEM>>>(x, sh, sw);
    wconv_kernel<<<(O_ * K_) / 256, 256>>>(w);
    gemm_kernel<<<dim3(2, 256), 512, SMEM_BYTES>>>(bias, out);
}